// round 13
// baseline (speedup 1.0000x reference)
#include <cuda_runtime.h>
#include <cuda_bf16.h>
#include <math.h>

// ---------------- problem constants ----------------
#define HID 768
#define NH 12
#define HD 64
#define FF 3072
#define NLAYER 12
#define CWIN 256
#define PDIM 128

#define B_DOC 2
#define S_DOC 2048
#define S_SUM 512
#define M_DOC (B_DOC * S_DOC)   // 4096
#define M_SUM (B_DOC * S_SUM)   // 1024

// weight-scratch layout (floats)
#define WBLK   (NLAYER * HID * HID)        // 7,077,888
#define WFFBLK (NLAYER * HID * FF)         // 28,311,552
#define OFF_WQ  0
#define OFF_WK  (OFF_WQ + WBLK)
#define OFF_WV  (OFF_WK + WBLK)
#define OFF_WO  (OFF_WV + WBLK)
#define OFF_W1  (OFF_WO + WBLK)
#define OFF_W2  (OFF_W1 + WFFBLK)
#define OFF_PW1 (OFF_W2 + WFFBLK)
#define OFF_PW2 (OFF_PW1 + HID * HID)
#define WR_TOTAL (OFF_PW2 + HID * PDIM)

// ---------------- scratch (device globals; no allocation allowed) -------
__device__ __align__(256) float g_xdoc[M_DOC * HID];
__device__ __align__(256) float g_xsum[M_SUM * HID];
__device__ __align__(256) float g_xr[M_DOC * HID];
__device__ __align__(256) float g_q[M_DOC * HID];
__device__ __align__(256) float g_k[M_DOC * HID];
__device__ __align__(256) float g_v[M_DOC * HID];
__device__ __align__(256) float g_a[M_DOC * HID];
__device__ __align__(256) float g_t[M_DOC * HID];
__device__ __align__(256) float g_h[M_DOC * FF];
__device__ __align__(256) float g_emb[16 * HID];
__device__ __align__(256) float g_p1[16 * HID];
__device__ __align__(256) float g_p2[16 * PDIM];
__device__ __align__(256) float g_wr[WR_TOTAL];

// ---------------- helpers ----------------
__device__ __forceinline__ float block_sum_256(float v) {
    __shared__ float sh[8];
    #pragma unroll
    for (int o = 16; o > 0; o >>= 1) v += __shfl_xor_sync(0xffffffffu, v, o);
    int w = threadIdx.x >> 5;
    if ((threadIdx.x & 31) == 0) sh[w] = v;
    __syncthreads();
    if (threadIdx.x < 8) {
        float r = sh[threadIdx.x];
        #pragma unroll
        for (int o = 4; o > 0; o >>= 1) r += __shfl_xor_sync(0x000000ffu, r, o);
        if (threadIdx.x == 0) sh[0] = r;
    }
    __syncthreads();
    float out = sh[0];
    __syncthreads();
    return out;
}

__device__ __forceinline__ unsigned smem_u32(const void* p) {
    return (unsigned)__cvta_generic_to_shared(p);
}

__device__ __forceinline__ void cp16(unsigned s, const void* g, bool pred) {
    asm volatile("cp.async.cg.shared.global [%0], [%1], 16, %2;\n"
                 :: "r"(s), "l"(g), "r"(pred ? 16 : 0));
}

__device__ __forceinline__ unsigned f2tf(float x) {
    unsigned r;
    asm("cvt.rna.tf32.f32 %0, %1;" : "=r"(r) : "f"(x));
    return r;
}

__device__ __forceinline__ float rndtf(float x) {
    return __uint_as_float(f2tf(x));
}

// split x = big + small (both exactly representable in tf32)
__device__ __forceinline__ void tfsplit(float x, unsigned& b, unsigned& s) {
    b = f2tf(x);
    s = f2tf(x - __uint_as_float(b));
}

__device__ __forceinline__ void mma8(float* c, const unsigned* a, const unsigned* b) {
    asm volatile(
        "mma.sync.aligned.m16n8k8.row.col.f32.tf32.tf32.f32 "
        "{%0,%1,%2,%3}, {%4,%5,%6,%7}, {%8,%9}, {%0,%1,%2,%3};"
        : "+f"(c[0]), "+f"(c[1]), "+f"(c[2]), "+f"(c[3])
        : "r"(a[0]), "r"(a[1]), "r"(a[2]), "r"(a[3]), "r"(b[0]), "r"(b[1]));
}

// ---------------- weight rounding (fp32 -> tf32-representable fp32) ------
__global__ void round_kernel(const float4* __restrict__ src,
                             float4* __restrict__ dst, int n4) {
    for (int i = blockIdx.x * blockDim.x + threadIdx.x; i < n4;
         i += gridDim.x * blockDim.x) {
        float4 v = src[i];
        v.x = rndtf(v.x); v.y = rndtf(v.y);
        v.z = rndtf(v.z); v.w = rndtf(v.w);
        dst[i] = v;
    }
}

// ---------------- embedding + layernorm (dual write: fp32 + tf32) --------
__global__ void embed_ln_kernel(const int* __restrict__ ids,
                                const float* __restrict__ wemb,
                                const float* __restrict__ pemb,
                                const float* __restrict__ tt,
                                const float* __restrict__ gam,
                                const float* __restrict__ bet,
                                float* __restrict__ out,
                                float* __restrict__ outr, int S) {
    int tok = blockIdx.x;
    int s = tok % S;
    int id = ids[tok];
    float vv[3];
    float sum = 0.f;
    #pragma unroll
    for (int kk = 0; kk < 3; kk++) {
        int h = threadIdx.x + kk * 256;
        vv[kk] = wemb[(size_t)id * HID + h] + pemb[(size_t)(s + 2) * HID + h] + tt[h];
        sum += vv[kk];
    }
    sum = block_sum_256(sum);
    float mu = sum * (1.f / HID);
    float q = 0.f;
    #pragma unroll
    for (int kk = 0; kk < 3; kk++) { float d = vv[kk] - mu; q += d * d; }
    q = block_sum_256(q);
    float r = rsqrtf(q * (1.f / HID) + 1e-5f);
    #pragma unroll
    for (int kk = 0; kk < 3; kk++) {
        int h = threadIdx.x + kk * 256;
        float o = (vv[kk] - mu) * r * gam[h] + bet[h];
        out[(size_t)tok * HID + h] = o;
        outr[(size_t)tok * HID + h] = rndtf(o);
    }
}

// ---------------- residual add + layernorm (dual write) -------------------
__global__ void add_ln_kernel(const float* __restrict__ xin,
                              const float* __restrict__ dres,
                              const float* __restrict__ gam,
                              const float* __restrict__ bet,
                              float* __restrict__ xout,
                              float* __restrict__ xoutr) {
    size_t base = (size_t)blockIdx.x * HID;
    float vv[3];
    float sum = 0.f;
    #pragma unroll
    for (int kk = 0; kk < 3; kk++) {
        int h = threadIdx.x + kk * 256;
        vv[kk] = xin[base + h] + dres[base + h];
        sum += vv[kk];
    }
    sum = block_sum_256(sum);
    float mu = sum * (1.f / HID);
    float q = 0.f;
    #pragma unroll
    for (int kk = 0; kk < 3; kk++) { float d = vv[kk] - mu; q += d * d; }
    q = block_sum_256(q);
    float r = rsqrtf(q * (1.f / HID) + 1e-5f);
    #pragma unroll
    for (int kk = 0; kk < 3; kk++) {
        int h = threadIdx.x + kk * 256;
        float o = (vv[kk] - mu) * r * gam[h] + bet[h];
        xout[base + h] = o;
        xoutr[base + h] = rndtf(o);
    }
}

// ---------------- tf32 tensor-core GEMM (pre-rounded operands) -----------
// EPI: 0 none, 1 gelu+round, 2 relu+round. Inputs A,B must already be
// tf32-representable fp32; inner loop does zero conversions.
__device__ __forceinline__ void gemm_load_stage(
    float (*As)[20], float (*Bs)[136],
    const float* __restrict__ A, const float* __restrict__ B,
    int row0, int col0, int k0, int M, int N, int K, int tid)
{
    #pragma unroll
    for (int it = 0; it < 2; it++) {
        int id = tid + it * 256;
        int r = id >> 2, qd = id & 3;
        int ar = row0 + r;
        int arc = (ar < M) ? ar : (M - 1);
        cp16(smem_u32(&As[r][qd * 4]), A + (size_t)arc * K + k0 + qd * 4, ar < M);
        int br = id >> 5, bc = id & 31;
        cp16(smem_u32(&Bs[br][bc * 4]), B + (size_t)(k0 + br) * N + col0 + bc * 4, true);
    }
    asm volatile("cp.async.commit_group;\n" ::: "memory");
}

template <int EPI>
__global__ __launch_bounds__(256, 2)
void mma_gemm(const float* __restrict__ A,
              const float* __restrict__ Bq, const float* __restrict__ Bk2,
              const float* __restrict__ Bv,
              const float* __restrict__ biq, const float* __restrict__ bik,
              const float* __restrict__ biv,
              float* __restrict__ Cq, float* __restrict__ Ck,
              float* __restrict__ Cv,
              int M, int N, int K) {
    const float* B    = (blockIdx.z == 0) ? Bq  : (blockIdx.z == 1) ? Bk2 : Bv;
    const float* bias = (blockIdx.z == 0) ? biq : (blockIdx.z == 1) ? bik : biv;
    float*       C    = (blockIdx.z == 0) ? Cq  : (blockIdx.z == 1) ? Ck  : Cv;

    __shared__ float As[2][128][20];
    __shared__ float Bs[2][16][136];

    int tid = threadIdx.x;
    int lane = tid & 31, warp = tid >> 5;
    int wm = warp & 1, wn = warp >> 1;
    int r8 = lane >> 2, c4 = lane & 3;
    int row0 = blockIdx.y * 128, col0 = blockIdx.x * 128;

    float acc[4][4][4];
    #pragma unroll
    for (int m = 0; m < 4; m++)
        #pragma unroll
        for (int n = 0; n < 4; n++)
            #pragma unroll
            for (int i = 0; i < 4; i++) acc[m][n][i] = 0.f;

    gemm_load_stage(As[0], Bs[0], A, B, row0, col0, 0, M, N, K, tid);

    int cur = 0;
    for (int k0 = 0; k0 < K; k0 += 16) {
        if (k0 + 16 < K) {
            gemm_load_stage(As[cur ^ 1], Bs[cur ^ 1], A, B, row0, col0, k0 + 16, M, N, K, tid);
            asm volatile("cp.async.wait_group 1;\n" ::: "memory");
        } else {
            asm volatile("cp.async.wait_group 0;\n" ::: "memory");
        }
        __syncthreads();

        #pragma unroll
        for (int kk = 0; kk < 16; kk += 8) {
            unsigned af[4][4], bf[4][2];
            #pragma unroll
            for (int m = 0; m < 4; m++) {
                int ar = wm * 64 + m * 16 + r8;
                af[m][0] = __float_as_uint(As[cur][ar][kk + c4]);
                af[m][1] = __float_as_uint(As[cur][ar + 8][kk + c4]);
                af[m][2] = __float_as_uint(As[cur][ar][kk + c4 + 4]);
                af[m][3] = __float_as_uint(As[cur][ar + 8][kk + c4 + 4]);
            }
            #pragma unroll
            for (int n = 0; n < 4; n++) {
                int bc = wn * 32 + n * 8 + r8;
                bf[n][0] = __float_as_uint(Bs[cur][kk + c4][bc]);
                bf[n][1] = __float_as_uint(Bs[cur][kk + c4 + 4][bc]);
            }
            #pragma unroll
            for (int m = 0; m < 4; m++)
                #pragma unroll
                for (int n = 0; n < 4; n++)
                    mma8(acc[m][n], af[m], bf[n]);
        }
        __syncthreads();
        cur ^= 1;
    }

    #pragma unroll
    for (int m = 0; m < 4; m++) {
        int r = row0 + wm * 64 + m * 16 + r8;
        #pragma unroll
        for (int n = 0; n < 4; n++) {
            int c = col0 + wn * 32 + n * 8 + c4 * 2;
            float b0 = bias[c], b1 = bias[c + 1];
            #pragma unroll
            for (int half = 0; half < 2; half++) {
                int rr = r + half * 8;
                if (rr >= M) continue;
                float v0 = acc[m][n][half * 2 + 0] + b0;
                float v1 = acc[m][n][half * 2 + 1] + b1;
                if (EPI == 1) {
                    v0 = 0.5f * v0 * (1.f + erff(v0 * 0.70710678118654752440f));
                    v1 = 0.5f * v1 * (1.f + erff(v1 * 0.70710678118654752440f));
                    v0 = rndtf(v0); v1 = rndtf(v1);
                }
                if (EPI == 2) {
                    v0 = rndtf(fmaxf(v0, 0.f)); v1 = rndtf(fmaxf(v1, 0.f));
                }
                C[(size_t)rr * N + c]     = v0;
                C[(size_t)rr * N + c + 1] = v1;
            }
        }
    }
}

// ---------------- tensor-core sliding-window attention --------------------
// grid: (nc*4, NH, B); block 128 threads (4 warps). Each block: 64 queries.
// Output is written tf32-rounded (it feeds only the O-projection GEMM).
__global__ __launch_bounds__(128)
void slide_attn_mma(const float* __restrict__ q, const float* __restrict__ k,
                    const float* __restrict__ v, const int* __restrict__ amask,
                    float* __restrict__ out, int S) {
    __shared__ float Qs[64][68];
    __shared__ float Ks[32][68];
    __shared__ float Vs[32][68];
    __shared__ float Ps[4][16][36];
    __shared__ int kval[32];

    int n = blockIdx.x >> 2, qt = blockIdx.x & 3;
    int h = blockIdx.y, b = blockIdx.z;
    int tid = threadIdx.x;
    int lane = tid & 31, warp = tid >> 5;
    int r8 = lane >> 2, c4 = lane & 3;
    int q0 = n * CWIN + qt * 64;

    #pragma unroll
    for (int it = 0; it < 8; it++) {
        int lin = tid + it * 128;
        int r = lin >> 4, d4 = (lin & 15) * 4;
        float4 qv = *(const float4*)&q[((size_t)(b * S + q0 + r)) * HID + h * HD + d4];
        qv.x *= 0.125f; qv.y *= 0.125f; qv.z *= 0.125f; qv.w *= 0.125f;
        *(float4*)&Qs[r][d4] = qv;
    }

    int iq_lo = qt * 64 + warp * 16 + r8;
    int iq_hi = iq_lo + 8;
    int kbase = n * CWIN - CWIN;

    float m_lo = -1e30f, m_hi = -1e30f, l_lo = 0.f, l_hi = 0.f;
    float o[8][4];
    #pragma unroll
    for (int nt = 0; nt < 8; nt++)
        #pragma unroll
        for (int i = 0; i < 4; i++) o[nt][i] = 0.f;

    int j_lo = qt * 64, j_hi = qt * 64 + 576;
    for (int j0 = j_lo; j0 < j_hi; j0 += 32) {
        __syncthreads();
        #pragma unroll
        for (int it = 0; it < 4; it++) {
            int lin = tid + it * 128;
            int jj = lin >> 4, d4 = (lin & 15) * 4;
            int g = kbase + j0 + jj;
            bool ok = (g >= 0) && (g < S) && (amask[b * S + g] != 0);
            float4 kv = make_float4(0.f, 0.f, 0.f, 0.f);
            float4 vv = make_float4(0.f, 0.f, 0.f, 0.f);
            if (ok) {
                size_t off = ((size_t)(b * S + g)) * HID + h * HD + d4;
                kv = *(const float4*)&k[off];
                vv = *(const float4*)&v[off];
            }
            *(float4*)&Ks[jj][d4] = kv;
            *(float4*)&Vs[jj][d4] = vv;
            if (d4 == 0) kval[jj] = ok ? 1 : 0;
        }
        __syncthreads();

        float sacc[4][4];
        #pragma unroll
        for (int j = 0; j < 4; j++)
            #pragma unroll
            for (int i = 0; i < 4; i++) sacc[j][i] = 0.f;

        #pragma unroll
        for (int kk = 0; kk < 64; kk += 8) {
            unsigned ab[4], as[4];
            tfsplit(Qs[warp * 16 + r8][kk + c4],          ab[0], as[0]);
            tfsplit(Qs[warp * 16 + r8 + 8][kk + c4],      ab[1], as[1]);
            tfsplit(Qs[warp * 16 + r8][kk + c4 + 4],      ab[2], as[2]);
            tfsplit(Qs[warp * 16 + r8 + 8][kk + c4 + 4],  ab[3], as[3]);
            #pragma unroll
            for (int j = 0; j < 4; j++) {
                unsigned bb[2], bs[2];
                tfsplit(Ks[j * 8 + r8][kk + c4],     bb[0], bs[0]);
                tfsplit(Ks[j * 8 + r8][kk + c4 + 4], bb[1], bs[1]);
                mma8(sacc[j], ab, bb);
                mma8(sacc[j], ab, bs);
                mma8(sacc[j], as, bb);
            }
        }

        #pragma unroll
        for (int j = 0; j < 4; j++) {
            int t0 = j0 + j * 8 + 2 * c4;
            int t1 = t0 + 1;
            bool k0 = kval[j * 8 + 2 * c4] != 0;
            bool k1 = kval[j * 8 + 2 * c4 + 1] != 0;
            if (!(k0 && t0 >= iq_lo && t0 <= iq_lo + 2 * CWIN)) sacc[j][0] = -1e9f;
            if (!(k1 && t1 >= iq_lo && t1 <= iq_lo + 2 * CWIN)) sacc[j][1] = -1e9f;
            if (!(k0 && t0 >= iq_hi && t0 <= iq_hi + 2 * CWIN)) sacc[j][2] = -1e9f;
            if (!(k1 && t1 >= iq_hi && t1 <= iq_hi + 2 * CWIN)) sacc[j][3] = -1e9f;
        }

        float mx_lo = -1e30f, mx_hi = -1e30f;
        #pragma unroll
        for (int j = 0; j < 4; j++) {
            mx_lo = fmaxf(mx_lo, fmaxf(sacc[j][0], sacc[j][1]));
            mx_hi = fmaxf(mx_hi, fmaxf(sacc[j][2], sacc[j][3]));
        }
        mx_lo = fmaxf(mx_lo, __shfl_xor_sync(0xffffffffu, mx_lo, 1));
        mx_lo = fmaxf(mx_lo, __shfl_xor_sync(0xffffffffu, mx_lo, 2));
        mx_hi = fmaxf(mx_hi, __shfl_xor_sync(0xffffffffu, mx_hi, 1));
        mx_hi = fmaxf(mx_hi, __shfl_xor_sync(0xffffffffu, mx_hi, 2));

        float mn_lo = fmaxf(m_lo, mx_lo);
        float mn_hi = fmaxf(m_hi, mx_hi);
        float corr_lo = __expf(m_lo - mn_lo);
        float corr_hi = __expf(m_hi - mn_hi);
        m_lo = mn_lo; m_hi = mn_hi;

        float rs_lo = 0.f, rs_hi = 0.f;
        #pragma unroll
        for (int j = 0; j < 4; j++) {
            sacc[j][0] = __expf(sacc[j][0] - mn_lo);
            sacc[j][1] = __expf(sacc[j][1] - mn_lo);
            sacc[j][2] = __expf(sacc[j][2] - mn_hi);
            sacc[j][3] = __expf(sacc[j][3] - mn_hi);
            rs_lo += sacc[j][0] + sacc[j][1];
            rs_hi += sacc[j][2] + sacc[j][3];
        }
        rs_lo += __shfl_xor_sync(0xffffffffu, rs_lo, 1);
        rs_lo += __shfl_xor_sync(0xffffffffu, rs_lo, 2);
        rs_hi += __shfl_xor_sync(0xffffffffu, rs_hi, 1);
        rs_hi += __shfl_xor_sync(0xffffffffu, rs_hi, 2);
        l_lo = l_lo * corr_lo + rs_lo;
        l_hi = l_hi * corr_hi + rs_hi;

        #pragma unroll
        for (int nt = 0; nt < 8; nt++) {
            o[nt][0] *= corr_lo; o[nt][1] *= corr_lo;
            o[nt][2] *= corr_hi; o[nt][3] *= corr_hi;
        }

        #pragma unroll
        for (int j = 0; j < 4; j++) {
            *(float2*)&Ps[warp][r8][j * 8 + 2 * c4]     = make_float2(sacc[j][0], sacc[j][1]);
            *(float2*)&Ps[warp][r8 + 8][j * 8 + 2 * c4] = make_float2(sacc[j][2], sacc[j][3]);
        }
        __syncwarp();

        #pragma unroll
        for (int kk2 = 0; kk2 < 32; kk2 += 8) {
            unsigned ab[4], as[4];
            tfsplit(Ps[warp][r8][kk2 + c4],         ab[0], as[0]);
            tfsplit(Ps[warp][r8 + 8][kk2 + c4],     ab[1], as[1]);
            tfsplit(Ps[warp][r8][kk2 + c4 + 4],     ab[2], as[2]);
            tfsplit(Ps[warp][r8 + 8][kk2 + c4 + 4], ab[3], as[3]);
            #pragma unroll
            for (int nt = 0; nt < 8; nt++) {
                unsigned bb[2], bs[2];
                tfsplit(Vs[kk2 + c4][nt * 8 + r8],     bb[0], bs[0]);
                tfsplit(Vs[kk2 + c4 + 4][nt * 8 + r8], bb[1], bs[1]);
                mma8(o[nt], ab, bb);
                mma8(o[nt], ab, bs);
                mma8(o[nt], as, bb);
            }
        }
        __syncwarp();
    }

    float inv_lo = 1.f / l_lo, inv_hi = 1.f / l_hi;
    int wrow_lo = q0 + warp * 16 + r8;
    int wrow_hi = wrow_lo + 8;
    #pragma unroll
    for (int nt = 0; nt < 8; nt++) {
        int c = h * HD + nt * 8 + 2 * c4;
        *(float2*)&out[(size_t)(b * S + wrow_lo) * HID + c] =
            make_float2(rndtf(o[nt][0] * inv_lo), rndtf(o[nt][1] * inv_lo));
        *(float2*)&out[(size_t)(b * S + wrow_hi) * HID + c] =
            make_float2(rndtf(o[nt][2] * inv_hi), rndtf(o[nt][3] * inv_hi));
    }
}

// ---------------- span pooling (output rounded; feeds GEMM) --------------
__global__ void span_pool_kernel(const float* __restrict__ masks,
                                 const float* __restrict__ seq,
                                 const int* __restrict__ sidx,
                                 float* __restrict__ emb, int S) {
    int t = blockIdx.x;
    int b = sidx[t];
    __shared__ float mch[256];
    float lenp = 0.f;
    for (int s = threadIdx.x; s < S; s += 256) lenp += masks[t * S + s];
    float len = block_sum_256(lenp);
    len = fmaxf(len, 1e-9f);
    float e[3] = {0.f, 0.f, 0.f};
    for (int s0 = 0; s0 < S; s0 += 256) {
        __syncthreads();
        mch[threadIdx.x] = masks[t * S + s0 + threadIdx.x];
        __syncthreads();
        for (int ss = 0; ss < 256; ss++) {
            float mv = mch[ss];
            size_t base = ((size_t)(b * S + s0 + ss)) * HID;
            #pragma unroll
            for (int kk = 0; kk < 3; kk++)
                e[kk] += mv * seq[base + threadIdx.x + kk * 256];
        }
    }
    float inv = 1.f / len;
    #pragma unroll
    for (int kk = 0; kk < 3; kk++)
        emb[t * HID + threadIdx.x + kk * 256] = rndtf(e[kk] * inv);
}

// ---------------- row-wise L2 normalize ----------------------------------
__global__ void l2norm_kernel(const float* __restrict__ p, float* __restrict__ out) {
    int t = blockIdx.x;
    float v = p[t * PDIM + threadIdx.x];
    float sq = v * v;
    __shared__ float sh[4];
    #pragma unroll
    for (int o = 16; o > 0; o >>= 1) sq += __shfl_xor_sync(0xffffffffu, sq, o);
    int w = threadIdx.x >> 5;
    if ((threadIdx.x & 31) == 0) sh[w] = sq;
    __syncthreads();
    float nrm = sqrtf(sh[0] + sh[1] + sh[2] + sh[3]);
    out[t * PDIM + threadIdx.x] = v / fmaxf(nrm, 1e-12f);
}

// ---------------- host orchestration ------------------------------------
struct Weights {
    const float *wemb, *pemb, *tt, *lng, *lnb;
    const float *bq, *bk, *bv, *bo;
    const float *ln1g, *ln1b, *b1, *b2, *ln2g, *ln2b;
    // pre-rounded weights (in g_wr)
    const float *Wq, *Wk, *Wv, *Wo, *W1, *W2;
};

static void run_encoder(const int* ids, const int* am, int B, int S, float* x,
                        float* xr, float* qb, float* kb, float* vb, float* ab,
                        float* tb, float* hb, const Weights& W) {
    int M = B * S;
    embed_ln_kernel<<<M, 256>>>(ids, W.wemb, W.pemb, W.tt, W.lng, W.lnb, x, xr, S);
    int nc = S / CWIN;
    dim3 gqkv(HID / 128, M / 128, 3);
    dim3 g768(HID / 128, M / 128, 1);
    dim3 gff(FF / 128, M / 128, 1);
    for (int l = 0; l < NLAYER; l++) {
        const float* wq = W.Wq + (size_t)l * HID * HID;
        const float* wk = W.Wk + (size_t)l * HID * HID;
        const float* wv = W.Wv + (size_t)l * HID * HID;
        const float* wo = W.Wo + (size_t)l * HID * HID;
        const float* w1 = W.W1 + (size_t)l * HID * FF;
        const float* w2 = W.W2 + (size_t)l * FF * HID;
        const float* bq = W.bq + l * HID;
        const float* bk = W.bk + l * HID;
        const float* bv = W.bv + l * HID;
        const float* bo = W.bo + l * HID;
        mma_gemm<0><<<gqkv, 256>>>(xr, wq, wk, wv, bq, bk, bv, qb, kb, vb, M, HID, HID);
        slide_attn_mma<<<dim3(nc * 4, NH, B), 128>>>(qb, kb, vb, am, ab, S);
        mma_gemm<0><<<g768, 256>>>(ab, wo, wo, wo, bo, bo, bo, tb, tb, tb, M, HID, HID);
        add_ln_kernel<<<M, 256>>>(x, tb, W.ln1g + l * HID, W.ln1b + l * HID, x, xr);
        mma_gemm<1><<<gff, 256>>>(xr, w1, w1, w1, W.b1 + l * FF, W.b1 + l * FF, W.b1 + l * FF,
                                  hb, hb, hb, M, FF, HID);
        mma_gemm<0><<<g768, 256>>>(hb, w2, w2, w2, W.b2 + l * HID, W.b2 + l * HID, W.b2 + l * HID,
                                   tb, tb, tb, M, HID, FF);
        add_ln_kernel<<<M, 256>>>(x, tb, W.ln2g + l * HID, W.ln2b + l * HID, x, xr);
    }
}

extern "C" void kernel_launch(void* const* d_in, const int* in_sizes, int n_in,
                              void* d_out, int out_size) {
    const int*   doc_ids   = (const int*)d_in[0];
    const int*   doc_am    = (const int*)d_in[1];
    const int*   sum_ids   = (const int*)d_in[2];
    const int*   sum_am    = (const int*)d_in[3];
    const float* og_masks  = (const float*)d_in[4];
    const float* llm_masks = (const float*)d_in[5];
    const int*   sidx      = (const int*)d_in[6];

    Weights W;
    W.wemb = (const float*)d_in[7];
    W.pemb = (const float*)d_in[8];
    W.tt   = (const float*)d_in[9];
    W.lng  = (const float*)d_in[10];
    W.lnb  = (const float*)d_in[11];
    const float* Wq_in = (const float*)d_in[12]; W.bq = (const float*)d_in[13];
    const float* Wk_in = (const float*)d_in[14]; W.bk = (const float*)d_in[15];
    const float* Wv_in = (const float*)d_in[16]; W.bv = (const float*)d_in[17];
    const float* Wo_in = (const float*)d_in[18]; W.bo = (const float*)d_in[19];
    W.ln1g = (const float*)d_in[20]; W.ln1b = (const float*)d_in[21];
    const float* W1_in = (const float*)d_in[22]; W.b1 = (const float*)d_in[23];
    const float* W2_in = (const float*)d_in[24]; W.b2 = (const float*)d_in[25];
    W.ln2g = (const float*)d_in[26]; W.ln2b = (const float*)d_in[27];
    const float* pW1 = (const float*)d_in[28];
    const float* pb1 = (const float*)d_in[29];
    const float* pW2 = (const float*)d_in[30];
    const float* pb2 = (const float*)d_in[31];
    float* out = (float*)d_out;

    float *xdoc, *xsum, *xr, *qb, *kb, *vb, *ab, *tb, *hb, *emb, *p1, *p2, *wr;
    cudaGetSymbolAddress((void**)&xdoc, g_xdoc);
    cudaGetSymbolAddress((void**)&xsum, g_xsum);
    cudaGetSymbolAddress((void**)&xr, g_xr);
    cudaGetSymbolAddress((void**)&qb, g_q);
    cudaGetSymbolAddress((void**)&kb, g_k);
    cudaGetSymbolAddress((void**)&vb, g_v);
    cudaGetSymbolAddress((void**)&ab, g_a);
    cudaGetSymbolAddress((void**)&tb, g_t);
    cudaGetSymbolAddress((void**)&hb, g_h);
    cudaGetSymbolAddress((void**)&emb, g_emb);
    cudaGetSymbolAddress((void**)&p1, g_p1);
    cudaGetSymbolAddress((void**)&p2, g_p2);
    cudaGetSymbolAddress((void**)&wr, g_wr);

    // pre-round all weights to tf32-representable fp32 (once per launch)
    round_kernel<<<2048, 256>>>((const float4*)Wq_in, (float4*)(wr + OFF_WQ), WBLK / 4);
    round_kernel<<<2048, 256>>>((const float4*)Wk_in, (float4*)(wr + OFF_WK), WBLK / 4);
    round_kernel<<<2048, 256>>>((const float4*)Wv_in, (float4*)(wr + OFF_WV), WBLK / 4);
    round_kernel<<<2048, 256>>>((const float4*)Wo_in, (float4*)(wr + OFF_WO), WBLK / 4);
    round_kernel<<<2048, 256>>>((const float4*)W1_in, (float4*)(wr + OFF_W1), WFFBLK / 4);
    round_kernel<<<2048, 256>>>((const float4*)W2_in, (float4*)(wr + OFF_W2), WFFBLK / 4);
    round_kernel<<<256, 256>>>((const float4*)pW1, (float4*)(wr + OFF_PW1), HID * HID / 4);
    round_kernel<<<96, 256>>>((const float4*)pW2, (float4*)(wr + OFF_PW2), HID * PDIM / 4);

    W.Wq = wr + OFF_WQ; W.Wk = wr + OFF_WK; W.Wv = wr + OFF_WV; W.Wo = wr + OFF_WO;
    W.W1 = wr + OFF_W1; W.W2 = wr + OFF_W2;
    const float* pW1r = wr + OFF_PW1;
    const float* pW2r = wr + OFF_PW2;

    run_encoder(doc_ids, doc_am, B_DOC, S_DOC, xdoc, xr, qb, kb, vb, ab, tb, hb, W);
    run_encoder(sum_ids, sum_am, B_DOC, S_SUM, xsum, xr, qb, kb, vb, ab, tb, hb, W);

    // human spans (doc)
    span_pool_kernel<<<16, 256>>>(og_masks, xdoc, sidx, emb, S_DOC);
    mma_gemm<2><<<dim3(HID / 128, 1, 1), 256>>>(emb, pW1r, pW1r, pW1r, pb1, pb1, pb1,
                                                p1, p1, p1, 16, HID, HID);
    mma_gemm<0><<<dim3(PDIM / 128, 1, 1), 256>>>(p1, pW2r, pW2r, pW2r, pb2, pb2, pb2,
                                                 p2, p2, p2, 16, PDIM, HID);
    l2norm_kernel<<<16, PDIM>>>(p2, out);

    // llm spans (summary)
    span_pool_kernel<<<16, 256>>>(llm_masks, xsum, sidx, emb, S_SUM);
    mma_gemm<2><<<dim3(HID / 128, 1, 1), 256>>>(emb, pW1r, pW1r, pW1r, pb1, pb1, pb1,
                                                p1, p1, p1, 16, HID, HID);
    mma_gemm<0><<<dim3(PDIM / 128, 1, 1), 256>>>(p1, pW2r, pW2r, pW2r, pb2, pb2, pb2,
                                                 p2, p2, p2, 16, PDIM, HID);
    l2norm_kernel<<<16, PDIM>>>(p2, out + 16 * PDIM);
}

// round 17
// speedup vs baseline: 1.4233x; 1.4233x over previous
#include <cuda_runtime.h>
#include <cuda_bf16.h>
#include <math.h>

// ---------------- problem constants ----------------
#define HID 768
#define NH 12
#define HD 64
#define FF 3072
#define NLAYER 12
#define CWIN 256
#define PDIM 128

#define B_DOC 2
#define S_DOC 2048
#define S_SUM 512
#define M_DOC (B_DOC * S_DOC)   // 4096
#define M_SUM (B_DOC * S_SUM)   // 1024

// ---------------- scratch (device globals; no allocation allowed) -------
// doc-encoder scratch
__device__ __align__(256) float g_xdoc[M_DOC * HID];
__device__ __align__(256) float g_q[M_DOC * HID];
__device__ __align__(256) float g_k[M_DOC * HID];
__device__ __align__(256) float g_v[M_DOC * HID];
__device__ __align__(256) float g_a[M_DOC * HID];
__device__ __align__(256) float g_t[M_DOC * HID];
__device__ __align__(256) float g_h[M_DOC * FF];
__device__ __align__(256) float g_emb[16 * HID];
__device__ __align__(256) float g_p1[16 * HID];
__device__ __align__(256) float g_p2[16 * PDIM];
// summary-encoder scratch (separate: may run concurrently on stream 1)
__device__ __align__(256) float g_xsum[M_SUM * HID];
__device__ __align__(256) float g_qs[M_SUM * HID];
__device__ __align__(256) float g_ks[M_SUM * HID];
__device__ __align__(256) float g_vs[M_SUM * HID];
__device__ __align__(256) float g_as[M_SUM * HID];
__device__ __align__(256) float g_ts[M_SUM * HID];
__device__ __align__(256) float g_hs[M_SUM * FF];
__device__ __align__(256) float g_embs[16 * HID];
__device__ __align__(256) float g_p1s[16 * HID];
__device__ __align__(256) float g_p2s[16 * PDIM];

// ---------------- helpers ----------------
__device__ __forceinline__ float block_sum_256(float v) {
    __shared__ float sh[8];
    #pragma unroll
    for (int o = 16; o > 0; o >>= 1) v += __shfl_xor_sync(0xffffffffu, v, o);
    int w = threadIdx.x >> 5;
    if ((threadIdx.x & 31) == 0) sh[w] = v;
    __syncthreads();
    if (threadIdx.x < 8) {
        float r = sh[threadIdx.x];
        #pragma unroll
        for (int o = 4; o > 0; o >>= 1) r += __shfl_xor_sync(0x000000ffu, r, o);
        if (threadIdx.x == 0) sh[0] = r;
    }
    __syncthreads();
    float out = sh[0];
    __syncthreads();
    return out;
}

__device__ __forceinline__ unsigned smem_u32(const void* p) {
    return (unsigned)__cvta_generic_to_shared(p);
}

__device__ __forceinline__ void cp16(unsigned s, const void* g, bool pred) {
    asm volatile("cp.async.cg.shared.global [%0], [%1], 16, %2;\n"
                 :: "r"(s), "l"(g), "r"(pred ? 16 : 0));
}

__device__ __forceinline__ unsigned f2tf(float x) {
    unsigned r;
    asm("cvt.rna.tf32.f32 %0, %1;" : "=r"(r) : "f"(x));
    return r;
}

// split x = big + small (both exactly representable in tf32)
__device__ __forceinline__ void tfsplit(float x, unsigned& b, unsigned& s) {
    b = f2tf(x);
    s = f2tf(x - __uint_as_float(b));
}

__device__ __forceinline__ void mma8(float* c, const unsigned* a, const unsigned* b) {
    asm volatile(
        "mma.sync.aligned.m16n8k8.row.col.f32.tf32.tf32.f32 "
        "{%0,%1,%2,%3}, {%4,%5,%6,%7}, {%8,%9}, {%0,%1,%2,%3};"
        : "+f"(c[0]), "+f"(c[1]), "+f"(c[2]), "+f"(c[3])
        : "r"(a[0]), "r"(a[1]), "r"(a[2]), "r"(a[3]), "r"(b[0]), "r"(b[1]));
}

// ---------------- embedding + layernorm ----------------------------------
__global__ void embed_ln_kernel(const int* __restrict__ ids,
                                const float* __restrict__ wemb,
                                const float* __restrict__ pemb,
                                const float* __restrict__ tt,
                                const float* __restrict__ gam,
                                const float* __restrict__ bet,
                                float* __restrict__ out, int S) {
    int tok = blockIdx.x;
    int s = tok % S;
    int id = ids[tok];
    float vv[3];
    float sum = 0.f;
    #pragma unroll
    for (int kk = 0; kk < 3; kk++) {
        int h = threadIdx.x + kk * 256;
        vv[kk] = wemb[(size_t)id * HID + h] + pemb[(size_t)(s + 2) * HID + h] + tt[h];
        sum += vv[kk];
    }
    sum = block_sum_256(sum);
    float mu = sum * (1.f / HID);
    float q = 0.f;
    #pragma unroll
    for (int kk = 0; kk < 3; kk++) { float d = vv[kk] - mu; q += d * d; }
    q = block_sum_256(q);
    float r = rsqrtf(q * (1.f / HID) + 1e-5f);
    #pragma unroll
    for (int kk = 0; kk < 3; kk++) {
        int h = threadIdx.x + kk * 256;
        out[(size_t)tok * HID + h] = (vv[kk] - mu) * r * gam[h] + bet[h];
    }
}

// ---------------- residual add + layernorm --------------------------------
__global__ void add_ln_kernel(const float* __restrict__ xin,
                              const float* __restrict__ dres,
                              const float* __restrict__ gam,
                              const float* __restrict__ bet,
                              float* __restrict__ xout) {
    size_t base = (size_t)blockIdx.x * HID;
    float vv[3];
    float sum = 0.f;
    #pragma unroll
    for (int kk = 0; kk < 3; kk++) {
        int h = threadIdx.x + kk * 256;
        vv[kk] = xin[base + h] + dres[base + h];
        sum += vv[kk];
    }
    sum = block_sum_256(sum);
    float mu = sum * (1.f / HID);
    float q = 0.f;
    #pragma unroll
    for (int kk = 0; kk < 3; kk++) { float d = vv[kk] - mu; q += d * d; }
    q = block_sum_256(q);
    float r = rsqrtf(q * (1.f / HID) + 1e-5f);
    #pragma unroll
    for (int kk = 0; kk < 3; kk++) {
        int h = threadIdx.x + kk * 256;
        xout[base + h] = (vv[kk] - mu) * r * gam[h] + bet[h];
    }
}

// ---------------- tf32 tensor-core GEMM -----------------------------------
__device__ __forceinline__ void gemm_load_stage(
    float (*As)[20], float (*Bs)[136],
    const float* __restrict__ A, const float* __restrict__ B,
    int row0, int col0, int k0, int M, int N, int K, int tid)
{
    #pragma unroll
    for (int it = 0; it < 2; it++) {
        int id = tid + it * 256;
        int r = id >> 2, qd = id & 3;
        int ar = row0 + r;
        int arc = (ar < M) ? ar : (M - 1);
        cp16(smem_u32(&As[r][qd * 4]), A + (size_t)arc * K + k0 + qd * 4, ar < M);
        int br = id >> 5, bc = id & 31;
        cp16(smem_u32(&Bs[br][bc * 4]), B + (size_t)(k0 + br) * N + col0 + bc * 4, true);
    }
    asm volatile("cp.async.commit_group;\n" ::: "memory");
}

template <int EPI>
__global__ __launch_bounds__(256, 2)
void mma_gemm(const float* __restrict__ A,
              const float* __restrict__ Bq, const float* __restrict__ Bk2,
              const float* __restrict__ Bv,
              const float* __restrict__ biq, const float* __restrict__ bik,
              const float* __restrict__ biv,
              float* __restrict__ Cq, float* __restrict__ Ck,
              float* __restrict__ Cv,
              int M, int N, int K) {
    const float* B    = (blockIdx.z == 0) ? Bq  : (blockIdx.z == 1) ? Bk2 : Bv;
    const float* bias = (blockIdx.z == 0) ? biq : (blockIdx.z == 1) ? bik : biv;
    float*       C    = (blockIdx.z == 0) ? Cq  : (blockIdx.z == 1) ? Ck  : Cv;

    __shared__ float As[2][128][20];
    __shared__ float Bs[2][16][136];

    int tid = threadIdx.x;
    int lane = tid & 31, warp = tid >> 5;
    int wm = warp & 1, wn = warp >> 1;
    int r8 = lane >> 2, c4 = lane & 3;
    int row0 = blockIdx.y * 128, col0 = blockIdx.x * 128;

    float acc[4][4][4];
    #pragma unroll
    for (int m = 0; m < 4; m++)
        #pragma unroll
        for (int n = 0; n < 4; n++)
            #pragma unroll
            for (int i = 0; i < 4; i++) acc[m][n][i] = 0.f;

    gemm_load_stage(As[0], Bs[0], A, B, row0, col0, 0, M, N, K, tid);

    int cur = 0;
    for (int k0 = 0; k0 < K; k0 += 16) {
        if (k0 + 16 < K) {
            gemm_load_stage(As[cur ^ 1], Bs[cur ^ 1], A, B, row0, col0, k0 + 16, M, N, K, tid);
            asm volatile("cp.async.wait_group 1;\n" ::: "memory");
        } else {
            asm volatile("cp.async.wait_group 0;\n" ::: "memory");
        }
        __syncthreads();

        #pragma unroll
        for (int kk = 0; kk < 16; kk += 8) {
            unsigned af[4][4], bf[4][2];
            #pragma unroll
            for (int m = 0; m < 4; m++) {
                int ar = wm * 64 + m * 16 + r8;
                af[m][0] = f2tf(As[cur][ar][kk + c4]);
                af[m][1] = f2tf(As[cur][ar + 8][kk + c4]);
                af[m][2] = f2tf(As[cur][ar][kk + c4 + 4]);
                af[m][3] = f2tf(As[cur][ar + 8][kk + c4 + 4]);
            }
            #pragma unroll
            for (int n = 0; n < 4; n++) {
                int bc = wn * 32 + n * 8 + r8;
                bf[n][0] = f2tf(Bs[cur][kk + c4][bc]);
                bf[n][1] = f2tf(Bs[cur][kk + c4 + 4][bc]);
            }
            #pragma unroll
            for (int m = 0; m < 4; m++)
                #pragma unroll
                for (int n = 0; n < 4; n++)
                    mma8(acc[m][n], af[m], bf[n]);
        }
        __syncthreads();
        cur ^= 1;
    }

    #pragma unroll
    for (int m = 0; m < 4; m++) {
        int r = row0 + wm * 64 + m * 16 + r8;
        #pragma unroll
        for (int n = 0; n < 4; n++) {
            int c = col0 + wn * 32 + n * 8 + c4 * 2;
            float b0 = bias[c], b1 = bias[c + 1];
            #pragma unroll
            for (int half = 0; half < 2; half++) {
                int rr = r + half * 8;
                if (rr >= M) continue;
                float v0 = acc[m][n][half * 2 + 0] + b0;
                float v1 = acc[m][n][half * 2 + 1] + b1;
                if (EPI == 1) {
                    v0 = 0.5f * v0 * (1.f + erff(v0 * 0.70710678118654752440f));
                    v1 = 0.5f * v1 * (1.f + erff(v1 * 0.70710678118654752440f));
                }
                if (EPI == 2) { v0 = fmaxf(v0, 0.f); v1 = fmaxf(v1, 0.f); }
                C[(size_t)rr * N + c]     = v0;
                C[(size_t)rr * N + c + 1] = v1;
            }
        }
    }
}

// ---------------- tensor-core sliding-window attention --------------------
__global__ __launch_bounds__(128)
void slide_attn_mma(const float* __restrict__ q, const float* __restrict__ k,
                    const float* __restrict__ v, const int* __restrict__ amask,
                    float* __restrict__ out, int S) {
    __shared__ float Qs[64][68];
    __shared__ float Ks[32][68];
    __shared__ float Vs[32][68];
    __shared__ float Ps[4][16][36];
    __shared__ int kval[32];

    int n = blockIdx.x >> 2, qt = blockIdx.x & 3;
    int h = blockIdx.y, b = blockIdx.z;
    int tid = threadIdx.x;
    int lane = tid & 31, warp = tid >> 5;
    int r8 = lane >> 2, c4 = lane & 3;
    int q0 = n * CWIN + qt * 64;

    #pragma unroll
    for (int it = 0; it < 8; it++) {
        int lin = tid + it * 128;
        int r = lin >> 4, d4 = (lin & 15) * 4;
        float4 qv = *(const float4*)&q[((size_t)(b * S + q0 + r)) * HID + h * HD + d4];
        qv.x *= 0.125f; qv.y *= 0.125f; qv.z *= 0.125f; qv.w *= 0.125f;
        *(float4*)&Qs[r][d4] = qv;
    }

    int iq_lo = qt * 64 + warp * 16 + r8;
    int iq_hi = iq_lo + 8;
    int kbase = n * CWIN - CWIN;

    float m_lo = -1e30f, m_hi = -1e30f, l_lo = 0.f, l_hi = 0.f;
    float o[8][4];
    #pragma unroll
    for (int nt = 0; nt < 8; nt++)
        #pragma unroll
        for (int i = 0; i < 4; i++) o[nt][i] = 0.f;

    int j_lo = qt * 64, j_hi = qt * 64 + 576;
    for (int j0 = j_lo; j0 < j_hi; j0 += 32) {
        __syncthreads();
        #pragma unroll
        for (int it = 0; it < 4; it++) {
            int lin = tid + it * 128;
            int jj = lin >> 4, d4 = (lin & 15) * 4;
            int g = kbase + j0 + jj;
            bool ok = (g >= 0) && (g < S) && (amask[b * S + g] != 0);
            float4 kv = make_float4(0.f, 0.f, 0.f, 0.f);
            float4 vv = make_float4(0.f, 0.f, 0.f, 0.f);
            if (ok) {
                size_t off = ((size_t)(b * S + g)) * HID + h * HD + d4;
                kv = *(const float4*)&k[off];
                vv = *(const float4*)&v[off];
            }
            *(float4*)&Ks[jj][d4] = kv;
            *(float4*)&Vs[jj][d4] = vv;
            if (d4 == 0) kval[jj] = ok ? 1 : 0;
        }
        __syncthreads();

        float sacc[4][4];
        #pragma unroll
        for (int j = 0; j < 4; j++)
            #pragma unroll
            for (int i = 0; i < 4; i++) sacc[j][i] = 0.f;

        #pragma unroll
        for (int kk = 0; kk < 64; kk += 8) {
            unsigned ab[4], as[4];
            tfsplit(Qs[warp * 16 + r8][kk + c4],          ab[0], as[0]);
            tfsplit(Qs[warp * 16 + r8 + 8][kk + c4],      ab[1], as[1]);
            tfsplit(Qs[warp * 16 + r8][kk + c4 + 4],      ab[2], as[2]);
            tfsplit(Qs[warp * 16 + r8 + 8][kk + c4 + 4],  ab[3], as[3]);
            #pragma unroll
            for (int j = 0; j < 4; j++) {
                unsigned bb[2], bs[2];
                tfsplit(Ks[j * 8 + r8][kk + c4],     bb[0], bs[0]);
                tfsplit(Ks[j * 8 + r8][kk + c4 + 4], bb[1], bs[1]);
                mma8(sacc[j], ab, bb);
                mma8(sacc[j], ab, bs);
                mma8(sacc[j], as, bb);
            }
        }

        #pragma unroll
        for (int j = 0; j < 4; j++) {
            int t0 = j0 + j * 8 + 2 * c4;
            int t1 = t0 + 1;
            bool k0 = kval[j * 8 + 2 * c4] != 0;
            bool k1 = kval[j * 8 + 2 * c4 + 1] != 0;
            if (!(k0 && t0 >= iq_lo && t0 <= iq_lo + 2 * CWIN)) sacc[j][0] = -1e9f;
            if (!(k1 && t1 >= iq_lo && t1 <= iq_lo + 2 * CWIN)) sacc[j][1] = -1e9f;
            if (!(k0 && t0 >= iq_hi && t0 <= iq_hi + 2 * CWIN)) sacc[j][2] = -1e9f;
            if (!(k1 && t1 >= iq_hi && t1 <= iq_hi + 2 * CWIN)) sacc[j][3] = -1e9f;
        }

        float mx_lo = -1e30f, mx_hi = -1e30f;
        #pragma unroll
        for (int j = 0; j < 4; j++) {
            mx_lo = fmaxf(mx_lo, fmaxf(sacc[j][0], sacc[j][1]));
            mx_hi = fmaxf(mx_hi, fmaxf(sacc[j][2], sacc[j][3]));
        }
        mx_lo = fmaxf(mx_lo, __shfl_xor_sync(0xffffffffu, mx_lo, 1));
        mx_lo = fmaxf(mx_lo, __shfl_xor_sync(0xffffffffu, mx_lo, 2));
        mx_hi = fmaxf(mx_hi, __shfl_xor_sync(0xffffffffu, mx_hi, 1));
        mx_hi = fmaxf(mx_hi, __shfl_xor_sync(0xffffffffu, mx_hi, 2));

        float mn_lo = fmaxf(m_lo, mx_lo);
        float mn_hi = fmaxf(m_hi, mx_hi);
        float corr_lo = __expf(m_lo - mn_lo);
        float corr_hi = __expf(m_hi - mn_hi);
        m_lo = mn_lo; m_hi = mn_hi;

        float rs_lo = 0.f, rs_hi = 0.f;
        #pragma unroll
        for (int j = 0; j < 4; j++) {
            sacc[j][0] = __expf(sacc[j][0] - mn_lo);
            sacc[j][1] = __expf(sacc[j][1] - mn_lo);
            sacc[j][2] = __expf(sacc[j][2] - mn_hi);
            sacc[j][3] = __expf(sacc[j][3] - mn_hi);
            rs_lo += sacc[j][0] + sacc[j][1];
            rs_hi += sacc[j][2] + sacc[j][3];
        }
        rs_lo += __shfl_xor_sync(0xffffffffu, rs_lo, 1);
        rs_lo += __shfl_xor_sync(0xffffffffu, rs_lo, 2);
        rs_hi += __shfl_xor_sync(0xffffffffu, rs_hi, 1);
        rs_hi += __shfl_xor_sync(0xffffffffu, rs_hi, 2);
        l_lo = l_lo * corr_lo + rs_lo;
        l_hi = l_hi * corr_hi + rs_hi;

        #pragma unroll
        for (int nt = 0; nt < 8; nt++) {
            o[nt][0] *= corr_lo; o[nt][1] *= corr_lo;
            o[nt][2] *= corr_hi; o[nt][3] *= corr_hi;
        }

        #pragma unroll
        for (int j = 0; j < 4; j++) {
            *(float2*)&Ps[warp][r8][j * 8 + 2 * c4]     = make_float2(sacc[j][0], sacc[j][1]);
            *(float2*)&Ps[warp][r8 + 8][j * 8 + 2 * c4] = make_float2(sacc[j][2], sacc[j][3]);
        }
        __syncwarp();

        #pragma unroll
        for (int kk2 = 0; kk2 < 32; kk2 += 8) {
            unsigned ab[4], as[4];
            tfsplit(Ps[warp][r8][kk2 + c4],         ab[0], as[0]);
            tfsplit(Ps[warp][r8 + 8][kk2 + c4],     ab[1], as[1]);
            tfsplit(Ps[warp][r8][kk2 + c4 + 4],     ab[2], as[2]);
            tfsplit(Ps[warp][r8 + 8][kk2 + c4 + 4], ab[3], as[3]);
            #pragma unroll
            for (int nt = 0; nt < 8; nt++) {
                unsigned bb[2], bs[2];
                tfsplit(Vs[kk2 + c4][nt * 8 + r8],     bb[0], bs[0]);
                tfsplit(Vs[kk2 + c4 + 4][nt * 8 + r8], bb[1], bs[1]);
                mma8(o[nt], ab, bb);
                mma8(o[nt], ab, bs);
                mma8(o[nt], as, bb);
            }
        }
        __syncwarp();
    }

    float inv_lo = 1.f / l_lo, inv_hi = 1.f / l_hi;
    int wrow_lo = q0 + warp * 16 + r8;
    int wrow_hi = wrow_lo + 8;
    #pragma unroll
    for (int nt = 0; nt < 8; nt++) {
        int c = h * HD + nt * 8 + 2 * c4;
        *(float2*)&out[(size_t)(b * S + wrow_lo) * HID + c] =
            make_float2(o[nt][0] * inv_lo, o[nt][1] * inv_lo);
        *(float2*)&out[(size_t)(b * S + wrow_hi) * HID + c] =
            make_float2(o[nt][2] * inv_hi, o[nt][3] * inv_hi);
    }
}

// ---------------- span pooling ------------------------------------------
__global__ void span_pool_kernel(const float* __restrict__ masks,
                                 const float* __restrict__ seq,
                                 const int* __restrict__ sidx,
                                 float* __restrict__ emb, int S) {
    int t = blockIdx.x;
    int b = sidx[t];
    __shared__ float mch[256];
    float lenp = 0.f;
    for (int s = threadIdx.x; s < S; s += 256) lenp += masks[t * S + s];
    float len = block_sum_256(lenp);
    len = fmaxf(len, 1e-9f);
    float e[3] = {0.f, 0.f, 0.f};
    for (int s0 = 0; s0 < S; s0 += 256) {
        __syncthreads();
        mch[threadIdx.x] = masks[t * S + s0 + threadIdx.x];
        __syncthreads();
        for (int ss = 0; ss < 256; ss++) {
            float mv = mch[ss];
            size_t base = ((size_t)(b * S + s0 + ss)) * HID;
            #pragma unroll
            for (int kk = 0; kk < 3; kk++)
                e[kk] += mv * seq[base + threadIdx.x + kk * 256];
        }
    }
    float inv = 1.f / len;
    #pragma unroll
    for (int kk = 0; kk < 3; kk++)
        emb[t * HID + threadIdx.x + kk * 256] = e[kk] * inv;
}

// ---------------- row-wise L2 normalize ----------------------------------
__global__ void l2norm_kernel(const float* __restrict__ p, float* __restrict__ out) {
    int t = blockIdx.x;
    float v = p[t * PDIM + threadIdx.x];
    float sq = v * v;
    __shared__ float sh[4];
    #pragma unroll
    for (int o = 16; o > 0; o >>= 1) sq += __shfl_xor_sync(0xffffffffu, sq, o);
    int w = threadIdx.x >> 5;
    if ((threadIdx.x & 31) == 0) sh[w] = sq;
    __syncthreads();
    float nrm = sqrtf(sh[0] + sh[1] + sh[2] + sh[3]);
    out[t * PDIM + threadIdx.x] = v / fmaxf(nrm, 1e-12f);
}

// ---------------- host orchestration ------------------------------------
struct Weights {
    const float *wemb, *pemb, *tt, *lng, *lnb;
    const float *Wq, *bq, *Wk, *bk, *Wv, *bv, *Wo, *bo;
    const float *ln1g, *ln1b, *W1, *b1, *W2, *b2, *ln2g, *ln2b;
};

static void run_encoder(const int* ids, const int* am, int B, int S, float* x,
                        float* qb, float* kb, float* vb, float* ab, float* tb,
                        float* hb, const Weights& W, cudaStream_t st) {
    int M = B * S;
    embed_ln_kernel<<<M, 256, 0, st>>>(ids, W.wemb, W.pemb, W.tt, W.lng, W.lnb, x, S);
    int nc = S / CWIN;
    dim3 gqkv(HID / 128, M / 128, 3);
    dim3 g768(HID / 128, M / 128, 1);
    dim3 gff(FF / 128, M / 128, 1);
    for (int l = 0; l < NLAYER; l++) {
        const float* wq = W.Wq + (size_t)l * HID * HID;
        const float* wk = W.Wk + (size_t)l * HID * HID;
        const float* wv = W.Wv + (size_t)l * HID * HID;
        const float* wo = W.Wo + (size_t)l * HID * HID;
        const float* w1 = W.W1 + (size_t)l * HID * FF;
        const float* w2 = W.W2 + (size_t)l * FF * HID;
        const float* bq = W.bq + l * HID;
        const float* bk = W.bk + l * HID;
        const float* bv = W.bv + l * HID;
        const float* bo = W.bo + l * HID;
        mma_gemm<0><<<gqkv, 256, 0, st>>>(x, wq, wk, wv, bq, bk, bv, qb, kb, vb, M, HID, HID);
        slide_attn_mma<<<dim3(nc * 4, NH, B), 128, 0, st>>>(qb, kb, vb, am, ab, S);
        mma_gemm<0><<<g768, 256, 0, st>>>(ab, wo, wo, wo, bo, bo, bo, tb, tb, tb, M, HID, HID);
        add_ln_kernel<<<M, 256, 0, st>>>(x, tb, W.ln1g + l * HID, W.ln1b + l * HID, x);
        mma_gemm<1><<<gff, 256, 0, st>>>(x, w1, w1, w1, W.b1 + l * FF, W.b1 + l * FF, W.b1 + l * FF,
                                         hb, hb, hb, M, FF, HID);
        mma_gemm<0><<<g768, 256, 0, st>>>(hb, w2, w2, w2, W.b2 + l * HID, W.b2 + l * HID, W.b2 + l * HID,
                                          tb, tb, tb, M, HID, FF);
        add_ln_kernel<<<M, 256, 0, st>>>(x, tb, W.ln2g + l * HID, W.ln2b + l * HID, x);
    }
}

static void run_spans(const float* masks, const float* seq, const int* sidx,
                      float* emb, float* p1, float* p2,
                      const float* pW1, const float* pb1,
                      const float* pW2, const float* pb2,
                      float* out, int S, cudaStream_t st) {
    span_pool_kernel<<<16, 256, 0, st>>>(masks, seq, sidx, emb, S);
    mma_gemm<2><<<dim3(HID / 128, 1, 1), 256, 0, st>>>(emb, pW1, pW1, pW1, pb1, pb1, pb1,
                                                       p1, p1, p1, 16, HID, HID);
    mma_gemm<0><<<dim3(PDIM / 128, 1, 1), 256, 0, st>>>(p1, pW2, pW2, pW2, pb2, pb2, pb2,
                                                        p2, p2, p2, 16, PDIM, HID);
    l2norm_kernel<<<16, PDIM, 0, st>>>(p2, out);
}

extern "C" void kernel_launch(void* const* d_in, const int* in_sizes, int n_in,
                              void* d_out, int out_size) {
    const int*   doc_ids   = (const int*)d_in[0];
    const int*   doc_am    = (const int*)d_in[1];
    const int*   sum_ids   = (const int*)d_in[2];
    const int*   sum_am    = (const int*)d_in[3];
    const float* og_masks  = (const float*)d_in[4];
    const float* llm_masks = (const float*)d_in[5];
    const int*   sidx      = (const int*)d_in[6];

    Weights W;
    W.wemb = (const float*)d_in[7];
    W.pemb = (const float*)d_in[8];
    W.tt   = (const float*)d_in[9];
    W.lng  = (const float*)d_in[10];
    W.lnb  = (const float*)d_in[11];
    W.Wq = (const float*)d_in[12]; W.bq = (const float*)d_in[13];
    W.Wk = (const float*)d_in[14]; W.bk = (const float*)d_in[15];
    W.Wv = (const float*)d_in[16]; W.bv = (const float*)d_in[17];
    W.Wo = (const float*)d_in[18]; W.bo = (const float*)d_in[19];
    W.ln1g = (const float*)d_in[20]; W.ln1b = (const float*)d_in[21];
    W.W1 = (const float*)d_in[22]; W.b1 = (const float*)d_in[23];
    W.W2 = (const float*)d_in[24]; W.b2 = (const float*)d_in[25];
    W.ln2g = (const float*)d_in[26]; W.ln2b = (const float*)d_in[27];
    const float* pW1 = (const float*)d_in[28];
    const float* pb1 = (const float*)d_in[29];
    const float* pW2 = (const float*)d_in[30];
    const float* pb2 = (const float*)d_in[31];
    float* out = (float*)d_out;

    float *xdoc, *qb, *kb, *vb, *ab, *tb, *hb, *emb, *p1, *p2;
    float *xsum, *qs, *ks, *vs, *as, *ts, *hs, *embs, *p1s, *p2s;
    cudaGetSymbolAddress((void**)&xdoc, g_xdoc);
    cudaGetSymbolAddress((void**)&qb, g_q);
    cudaGetSymbolAddress((void**)&kb, g_k);
    cudaGetSymbolAddress((void**)&vb, g_v);
    cudaGetSymbolAddress((void**)&ab, g_a);
    cudaGetSymbolAddress((void**)&tb, g_t);
    cudaGetSymbolAddress((void**)&hb, g_h);
    cudaGetSymbolAddress((void**)&emb, g_emb);
    cudaGetSymbolAddress((void**)&p1, g_p1);
    cudaGetSymbolAddress((void**)&p2, g_p2);
    cudaGetSymbolAddress((void**)&xsum, g_xsum);
    cudaGetSymbolAddress((void**)&qs, g_qs);
    cudaGetSymbolAddress((void**)&ks, g_ks);
    cudaGetSymbolAddress((void**)&vs, g_vs);
    cudaGetSymbolAddress((void**)&as, g_as);
    cudaGetSymbolAddress((void**)&ts, g_ts);
    cudaGetSymbolAddress((void**)&hs, g_hs);
    cudaGetSymbolAddress((void**)&embs, g_embs);
    cudaGetSymbolAddress((void**)&p1s, g_p1s);
    cudaGetSymbolAddress((void**)&p2s, g_p2s);

    // side stream + fork/join events. Created once on the first call (the
    // correctness run, outside graph capture). If ANY creation fails, fall
    // back to fully-serial single-stream execution (proven-correct path).
    static cudaStream_t s1 = nullptr;
    static cudaEvent_t evFork = nullptr, evJoin = nullptr;
    static int overlap_state = 0;   // 0 = uninit, 1 = ok, -1 = disabled
    if (overlap_state == 0) {
        overlap_state = 1;
        if (cudaStreamCreateWithFlags(&s1, cudaStreamNonBlocking) != cudaSuccess)
            overlap_state = -1;
        if (overlap_state == 1 &&
            cudaEventCreateWithFlags(&evFork, cudaEventDisableTiming) != cudaSuccess)
            overlap_state = -1;
        if (overlap_state == 1 &&
            cudaEventCreateWithFlags(&evJoin, cudaEventDisableTiming) != cudaSuccess)
            overlap_state = -1;
    }

    if (overlap_state == 1) {
        // fork: summary branch runs concurrently on s1
        cudaEventRecord(evFork, 0);
        cudaStreamWaitEvent(s1, evFork, 0);

        // doc branch (stream 0): encoder + human spans -> out[0:16*PDIM)
        run_encoder(doc_ids, doc_am, B_DOC, S_DOC, xdoc, qb, kb, vb, ab, tb, hb, W, 0);
        run_spans(og_masks, xdoc, sidx, emb, p1, p2, pW1, pb1, pW2, pb2, out, S_DOC, 0);

        // summary branch (s1): encoder + llm spans -> out[16*PDIM:32*PDIM)
        run_encoder(sum_ids, sum_am, B_DOC, S_SUM, xsum, qs, ks, vs, as, ts, hs, W, s1);
        run_spans(llm_masks, xsum, sidx, embs, p1s, p2s, pW1, pb1, pW2, pb2,
                  out + 16 * PDIM, S_SUM, s1);

        // join back into the capture-origin stream
        cudaEventRecord(evJoin, s1);
        cudaStreamWaitEvent(0, evJoin, 0);
    } else {
        // serial fallback (identical to the proven single-stream version)
        run_encoder(doc_ids, doc_am, B_DOC, S_DOC, xdoc, qb, kb, vb, ab, tb, hb, W, 0);
        run_spans(og_masks, xdoc, sidx, emb, p1, p2, pW1, pb1, pW2, pb2, out, S_DOC, 0);
        run_encoder(sum_ids, sum_am, B_DOC, S_SUM, xsum, qs, ks, vs, as, ts, hs, W, 0);
        run_spans(llm_masks, xsum, sidx, embs, p1s, p2s, pW1, pb1, pW2, pb2,
                  out + 16 * PDIM, S_SUM, 0);
    }
}